// round 8
// baseline (speedup 1.0000x reference)
#include <cuda_runtime.h>

#define EPS 1e-6f
#define Q 128
#define HW 65536            // 256*256
#define NW 8                // columns (warps) per block
#define THREADS 256

__device__ float g_wt[Q];   // softmax(weights) * 128, precomputed once

// ---------------------------------------------------------------------------
// Prep kernel: one warp computes wt = softmax(weights) * 128
// ---------------------------------------------------------------------------
__global__ void softmax_wt_kernel(const float* __restrict__ w) {
    int l = threadIdx.x;                       // 0..31
    float v0 = w[l * 4 + 0], v1 = w[l * 4 + 1];
    float v2 = w[l * 4 + 2], v3 = w[l * 4 + 3];
    float m = fmaxf(fmaxf(v0, v1), fmaxf(v2, v3));
    #pragma unroll
    for (int o = 16; o; o >>= 1) m = fmaxf(m, __shfl_xor_sync(0xffffffffu, m, o));
    float e0 = expf(v0 - m), e1 = expf(v1 - m);
    float e2 = expf(v2 - m), e3 = expf(v3 - m);
    float s = e0 + e1 + e2 + e3;
    #pragma unroll
    for (int o = 16; o; o >>= 1) s += __shfl_xor_sync(0xffffffffu, s, o);
    float scale = 128.0f / s;
    g_wt[l * 4 + 0] = e0 * scale;
    g_wt[l * 4 + 1] = e1 * scale;
    g_wt[l * 4 + 2] = e2 * scale;
    g_wt[l * 4 + 3] = e3 * scale;
}

// ---------------------------------------------------------------------------
// Main kernel: block = 256 threads = 8 warps; each warp ranks one column of
// 128 values (along dim q). XOR-swizzled SMEM transpose, warp-register
// bitonic sort (descending), binary-search rank, exact tie fixup.
// ---------------------------------------------------------------------------
__global__ void __launch_bounds__(THREADS) rank_weight_kernel(
        const float* __restrict__ x, float* __restrict__ out) {
    __shared__ __align__(16) float A[NW * Q];   // original values (transposed), later reused for output
    __shared__ __align__(16) float S[NW * Q];   // sorted values per column
    __shared__ float wt_s[Q];

    int t = threadIdx.x;
    if (t < Q) wt_s[t] = g_wt[t];

    // Column base: 8 consecutive flattened (b, h*w) columns per block.
    long long c0  = (long long)blockIdx.x * NW;
    int       b   = (int)(c0 >> 16);            // HW = 65536 columns per batch
    int       rem = (int)(c0 & (HW - 1));
    const float* xb = x   + (long long)b * (Q * (long long)HW) + rem;
    float*       ob = out + (long long)b * (Q * (long long)HW) + rem;

    // ---- Phase 1: coalesced load, transpose into swizzled SMEM ----
    {
        int q = t >> 1;            // 128 rows, 2 threads per row
        int g = t & 1;             // which float4 group: w_local = 4g .. 4g+3
        float4 f = *reinterpret_cast<const float4*>(xb + (long long)q * HW + 4 * g);
        float vv[4] = {f.x, f.y, f.z, f.w};
        #pragma unroll
        for (int j = 0; j < 4; j++) {
            int w = 4 * g + j;
            A[w * Q + (q ^ (w << 2))] = vv[j];
        }
    }
    __syncthreads();

    int lane = t & 31;
    int w    = t >> 5;             // warp id = local column
    int sw   = w << 2;             // swizzle constant for this column

    // ---- Phase 2: read column (q = 4*lane + r), sort descending ----
    float4 cv = *reinterpret_cast<const float4*>(&A[w * Q + ((lane << 2) ^ sw)]);
    float v[4]    = {cv.x, cv.y, cv.z, cv.w};
    float orig[4] = {cv.x, cv.y, cv.z, cv.w};

    #pragma unroll
    for (int k = 2; k <= 128; k <<= 1) {
        #pragma unroll
        for (int j = k >> 1; j > 0; j >>= 1) {
            if (j >= 4) {
                // cross-lane butterfly; direction uniform across a thread's 4 slots
                #pragma unroll
                for (int r = 0; r < 4; r++) {
                    float o  = __shfl_xor_sync(0xffffffffu, v[r], j >> 2);
                    int   id = (lane << 2) + r;
                    bool keep_max = (((id & k) == 0) == ((id & j) == 0));
                    float mx = fmaxf(v[r], o), mn = fminf(v[r], o);
                    v[r] = keep_max ? mx : mn;
                }
            } else if (j == 2) {
                #pragma unroll
                for (int r = 0; r < 2; r++) {
                    int  id = (lane << 2) + r;          // (id & 2) == 0 here
                    bool keep_max = ((id & k) == 0);
                    float a = v[r], bb = v[r + 2];
                    float mx = fmaxf(a, bb), mn = fminf(a, bb);
                    v[r]     = keep_max ? mx : mn;
                    v[r + 2] = keep_max ? mn : mx;
                }
            } else {  // j == 1
                #pragma unroll
                for (int r = 0; r < 4; r += 2) {
                    int  id = (lane << 2) + r;          // (id & 1) == 0 here
                    bool keep_max = ((id & k) == 0);
                    float a = v[r], bb = v[r + 1];
                    float mx = fmaxf(a, bb), mn = fminf(a, bb);
                    v[r]     = keep_max ? mx : mn;
                    v[r + 1] = keep_max ? mn : mx;
                }
            }
        }
    }

    // store sorted column (descending: S[p] = p-th largest)
    *reinterpret_cast<float4*>(&S[w * Q + ((lane << 2) ^ sw)]) =
        make_float4(v[0], v[1], v[2], v[3]);
    __syncwarp();

    // ---- Phase 3: rank via binary search (count strictly greater), tie fixup ----
    const float* Scol = &S[w * Q];
    const float* Acol = &A[w * Q];
    float res[4];
    #pragma unroll
    for (int r = 0; r < 4; r++) {
        float xv  = orig[r];
        int   pos = 0;                        // will equal #{j : x_j > xv}
        #pragma unroll
        for (int step = 64; step >= 1; step >>= 1) {
            if (Scol[(pos + step - 1) ^ sw] > xv) pos += step;
        }
        int rank = pos;
        // exact stable tie handling (rare): duplicates sit at pos, pos+1, ...
        if (pos + 1 < Q && Scol[(pos + 1) ^ sw] == xv) {
            int i = (lane << 2) + r;          // this element's original q index
            int eq = 0;
            for (int jj = 0; jj < i; jj++)
                eq += (Acol[jj ^ sw] == xv) ? 1 : 0;
            rank = pos + eq;
        }
        float rs;
        asm("rsqrt.approx.f32 %0, %1;" : "=f"(rs) : "f"(__fmaf_rn(xv, xv, EPS)));
        res[r] = wt_s[rank] * rs;
    }

    // all lanes of this warp are done reading Acol -> safe to overwrite own column
    __syncwarp();
    *reinterpret_cast<float4*>(&A[w * Q + ((lane << 2) ^ sw)]) =
        make_float4(res[0], res[1], res[2], res[3]);
    __syncthreads();

    // ---- Phase 4: transpose back, coalesced store ----
    {
        int q = t >> 1;
        int g = t & 1;
        float o0 = A[(4 * g + 0) * Q + (q ^ ((4 * g + 0) << 2))];
        float o1 = A[(4 * g + 1) * Q + (q ^ ((4 * g + 1) << 2))];
        float o2 = A[(4 * g + 2) * Q + (q ^ ((4 * g + 2) << 2))];
        float o3 = A[(4 * g + 3) * Q + (q ^ ((4 * g + 3) << 2))];
        *reinterpret_cast<float4*>(ob + (long long)q * HW + 4 * g) =
            make_float4(o0, o1, o2, o3);
    }
}

// ---------------------------------------------------------------------------
extern "C" void kernel_launch(void* const* d_in, const int* in_sizes, int n_in,
                              void* d_out, int out_size) {
    const float* x  = (const float*)d_in[0];
    const float* wt = (const float*)d_in[1];
    if (n_in >= 2 && in_sizes[0] == Q) {  // defensive: metadata order swap
        const float* tmp = x; x = wt; wt = tmp;
    }
    float* out = (float*)d_out;

    softmax_wt_kernel<<<1, 32>>>(wt);

    // total columns = 8 * 256 * 256 = 524288; NW columns per block
    int total_cols = 8 * HW;
    int blocks = total_cols / NW;          // 65536
    rank_weight_kernel<<<blocks, THREADS>>>(x, out);
}

// round 9
// speedup vs baseline: 1.0423x; 1.0423x over previous
#include <cuda_runtime.h>

#define EPS 1e-6f
#define Q 128
#define HW 65536            // 256*256
#define NW 8                // columns (warps) per block
#define THREADS 256
#define SSTRIDE 132         // sorted-column stride (128 data + sentinel + pad)

__device__ float g_wt[Q];   // softmax(weights) * 128, precomputed once

// ---------------------------------------------------------------------------
// Prep kernel: one warp computes wt = softmax(weights) * 128
// ---------------------------------------------------------------------------
__global__ void softmax_wt_kernel(const float* __restrict__ w) {
    int l = threadIdx.x;                       // 0..31
    float v0 = w[l * 4 + 0], v1 = w[l * 4 + 1];
    float v2 = w[l * 4 + 2], v3 = w[l * 4 + 3];
    float m = fmaxf(fmaxf(v0, v1), fmaxf(v2, v3));
    #pragma unroll
    for (int o = 16; o; o >>= 1) m = fmaxf(m, __shfl_xor_sync(0xffffffffu, m, o));
    float e0 = expf(v0 - m), e1 = expf(v1 - m);
    float e2 = expf(v2 - m), e3 = expf(v3 - m);
    float s = e0 + e1 + e2 + e3;
    #pragma unroll
    for (int o = 16; o; o >>= 1) s += __shfl_xor_sync(0xffffffffu, s, o);
    float scale = 128.0f / s;
    g_wt[l * 4 + 0] = e0 * scale;
    g_wt[l * 4 + 1] = e1 * scale;
    g_wt[l * 4 + 2] = e2 * scale;
    g_wt[l * 4 + 3] = e3 * scale;
}

// All-FMA-pipe rsqrt: magic seed (shift via IMAD.HI) + 2 Newton iterations.
// Max rel err ~5e-6 for a in [1e-6, huge) — far inside the 1e-3 budget.
__device__ __forceinline__ float rsqrt_newton(float a) {
    unsigned i  = __float_as_uint(a);
    unsigned h  = __umulhi(i, 0x80000000u);          // i >> 1, on the fma pipe
    float    y  = __uint_as_float(0x5f3759dfu - h);
    float    h0 = -0.5f * a;
    y = y * __fmaf_rn(h0 * y, y, 1.5f);
    y = y * __fmaf_rn(h0 * y, y, 1.5f);
    return y;
}

__device__ __forceinline__ float rsqrt_mufu(float a) {
    float rs;
    asm("rsqrt.approx.f32 %0, %1;" : "=f"(rs) : "f"(a));
    return rs;
}

// ---------------------------------------------------------------------------
// Main kernel: block = 256 threads = 8 warps; each warp ranks one column of
// 128 values (along dim q). XOR-swizzled SMEM transpose, warp-register
// bitonic sort (descending), byte-offset binary-search rank, exact tie fixup.
// ---------------------------------------------------------------------------
__global__ void __launch_bounds__(THREADS) rank_weight_kernel(
        const float* __restrict__ x, float* __restrict__ out) {
    __shared__ __align__(16) float A[NW * Q];        // originals (swizzled), reused for output
    __shared__ __align__(16) float S[NW * SSTRIDE];  // sorted values per column (unswizzled)
    __shared__ float wt_s[Q];

    int t = threadIdx.x;
    if (t < Q) wt_s[t] = g_wt[t];

    // Column base: 8 consecutive flattened (b, h*w) columns per block.
    long long c0  = (long long)blockIdx.x * NW;
    int       b   = (int)(c0 >> 16);            // HW = 65536 columns per batch
    int       rem = (int)(c0 & (HW - 1));
    const float* xb = x   + (long long)b * (Q * (long long)HW) + rem;
    float*       ob = out + (long long)b * (Q * (long long)HW) + rem;

    // ---- Phase 1: coalesced load, transpose into swizzled SMEM ----
    {
        int q = t >> 1;            // 128 rows, 2 threads per row
        int g = t & 1;             // which float4 group: w_local = 4g .. 4g+3
        float4 f = *reinterpret_cast<const float4*>(xb + (long long)q * HW + 4 * g);
        float vv[4] = {f.x, f.y, f.z, f.w};
        #pragma unroll
        for (int j = 0; j < 4; j++) {
            int w = 4 * g + j;
            A[w * Q + (q ^ (w << 2))] = vv[j];
        }
    }
    __syncthreads();

    int lane = t & 31;
    int w    = t >> 5;             // warp id = local column
    int sw   = w << 2;             // swizzle constant for this column

    // ---- Phase 2: read column (q = 4*lane + r), sort descending ----
    float4 cv = *reinterpret_cast<const float4*>(&A[w * Q + ((lane << 2) ^ sw)]);
    float v[4]    = {cv.x, cv.y, cv.z, cv.w};
    float orig[4] = {cv.x, cv.y, cv.z, cv.w};

    #pragma unroll
    for (int k = 2; k <= 128; k <<= 1) {
        #pragma unroll
        for (int j = k >> 1; j > 0; j >>= 1) {
            if (j >= 4) {
                // cross-lane butterfly; direction uniform across a thread's 4 slots
                #pragma unroll
                for (int r = 0; r < 4; r++) {
                    float o  = __shfl_xor_sync(0xffffffffu, v[r], j >> 2);
                    int   id = (lane << 2) + r;
                    bool keep_max = (((id & k) == 0) == ((id & j) == 0));
                    float mx = fmaxf(v[r], o), mn = fminf(v[r], o);
                    v[r] = keep_max ? mx : mn;
                }
            } else if (j == 2) {
                #pragma unroll
                for (int r = 0; r < 2; r++) {
                    int  id = (lane << 2) + r;          // (id & 2) == 0 here
                    bool keep_max = ((id & k) == 0);
                    float a = v[r], bb = v[r + 2];
                    float mx = fmaxf(a, bb), mn = fminf(a, bb);
                    v[r]     = keep_max ? mx : mn;
                    v[r + 2] = keep_max ? mn : mx;
                }
            } else {  // j == 1
                #pragma unroll
                for (int r = 0; r < 4; r += 2) {
                    int  id = (lane << 2) + r;          // (id & 1) == 0 here
                    bool keep_max = ((id & k) == 0);
                    float a = v[r], bb = v[r + 1];
                    float mx = fmaxf(a, bb), mn = fminf(a, bb);
                    v[r]     = keep_max ? mx : mn;
                    v[r + 1] = keep_max ? mn : mx;
                }
            }
        }
    }

    // store sorted column UNSWIZZLED (descending: S[p] = p-th largest)
    float* Scol = &S[w * SSTRIDE];
    *reinterpret_cast<float4*>(&Scol[lane << 2]) =
        make_float4(v[0], v[1], v[2], v[3]);
    if (lane == 0) Scol[Q] = __int_as_float(0xff800000);   // -inf sentinel
    __syncwarp();

    // ---- Phase 3: rank via byte-offset binary search, exact tie fixup ----
    const char*  Sb   = reinterpret_cast<const char*>(Scol);
    const float* Acol = &A[w * Q];
    bool use_newton = (w < 7);   // per-warp uniform: 7/32 of slots use FFMA rsqrt
    float res[4];
    #pragma unroll
    for (int r = 0; r < 4; r++) {
        float xv   = orig[r];
        int   posb = 0;                       // byte offset; final = 4*#{x_j > xv}
        #pragma unroll
        for (int stepb = 256; stepb >= 4; stepb >>= 1) {
            float probe = *reinterpret_cast<const float*>(Sb + (posb + (stepb - 4)));
            if (probe > xv) posb += stepb;
        }
        // tie test: sentinel at Q guards posb == 508
        float nxt = *reinterpret_cast<const float*>(Sb + posb + 4);
        float wv;
        if (nxt == xv) {
            // exact stable tie handling (rare): duplicates sit at pos, pos+1, ...
            int i = (lane << 2) + r;          // this element's original q index
            int eq = 0;
            for (int jj = 0; jj < i; jj++)
                eq += (Acol[jj ^ sw] == xv) ? 1 : 0;
            wv = wt_s[(posb >> 2) + eq];
        } else {
            wv = *reinterpret_cast<const float*>(
                     reinterpret_cast<const char*>(wt_s) + posb);
        }
        float a = __fmaf_rn(xv, xv, EPS);
        float rs;
        if (r == 0) {
            if (use_newton) rs = rsqrt_newton(a);
            else            rs = rsqrt_mufu(a);
        } else {
            rs = rsqrt_mufu(a);
        }
        res[r] = wv * rs;
    }

    // all lanes of this warp are done reading Acol -> safe to overwrite own column
    __syncwarp();
    *reinterpret_cast<float4*>(&A[w * Q + ((lane << 2) ^ sw)]) =
        make_float4(res[0], res[1], res[2], res[3]);
    __syncthreads();

    // ---- Phase 4: transpose back, coalesced store ----
    {
        int q = t >> 1;
        int g = t & 1;
        float o0 = A[(4 * g + 0) * Q + (q ^ ((4 * g + 0) << 2))];
        float o1 = A[(4 * g + 1) * Q + (q ^ ((4 * g + 1) << 2))];
        float o2 = A[(4 * g + 2) * Q + (q ^ ((4 * g + 2) << 2))];
        float o3 = A[(4 * g + 3) * Q + (q ^ ((4 * g + 3) << 2))];
        *reinterpret_cast<float4*>(ob + (long long)q * HW + 4 * g) =
            make_float4(o0, o1, o2, o3);
    }
}

// ---------------------------------------------------------------------------
extern "C" void kernel_launch(void* const* d_in, const int* in_sizes, int n_in,
                              void* d_out, int out_size) {
    const float* x  = (const float*)d_in[0];
    const float* wt = (const float*)d_in[1];
    if (n_in >= 2 && in_sizes[0] == Q) {  // defensive: metadata order swap
        const float* tmp = x; x = wt; wt = tmp;
    }
    float* out = (float*)d_out;

    softmax_wt_kernel<<<1, 32>>>(wt);

    // total columns = 8 * 256 * 256 = 524288; NW columns per block
    int total_cols = 8 * HW;
    int blocks = total_cols / NW;          // 65536
    rank_weight_kernel<<<blocks, THREADS>>>(x, out);
}

// round 10
// speedup vs baseline: 1.1182x; 1.0729x over previous
#include <cuda_runtime.h>

#define EPS 1e-6f
#define Q 128
#define HW 65536            // 256*256
#define NW 8                // columns (warps) per block
#define THREADS 256

__device__ float g_wt[Q];   // softmax(weights) * 128, precomputed once

// ---------------------------------------------------------------------------
// Prep kernel: one warp computes wt = softmax(weights) * 128
// ---------------------------------------------------------------------------
__global__ void softmax_wt_kernel(const float* __restrict__ w) {
    int l = threadIdx.x;                       // 0..31
    float v0 = w[l * 4 + 0], v1 = w[l * 4 + 1];
    float v2 = w[l * 4 + 2], v3 = w[l * 4 + 3];
    float m = fmaxf(fmaxf(v0, v1), fmaxf(v2, v3));
    #pragma unroll
    for (int o = 16; o; o >>= 1) m = fmaxf(m, __shfl_xor_sync(0xffffffffu, m, o));
    float e0 = expf(v0 - m), e1 = expf(v1 - m);
    float e2 = expf(v2 - m), e3 = expf(v3 - m);
    float s = e0 + e1 + e2 + e3;
    #pragma unroll
    for (int o = 16; o; o >>= 1) s += __shfl_xor_sync(0xffffffffu, s, o);
    float scale = 128.0f / s;
    g_wt[l * 4 + 0] = e0 * scale;
    g_wt[l * 4 + 1] = e1 * scale;
    g_wt[l * 4 + 2] = e2 * scale;
    g_wt[l * 4 + 3] = e3 * scale;
}

// ---------------------------------------------------------------------------
// Main kernel: block = 256 threads = 8 warps; each warp ranks one column of
// 128 values (dim q). Swizzled SMEM transpose, warp-register bitonic sort,
// bit-reversed conflict-free binary-search rank, ballot-gated exact tie path.
// ---------------------------------------------------------------------------
__global__ void __launch_bounds__(THREADS) rank_weight_kernel(
        const float* __restrict__ x, float* __restrict__ out) {
    __shared__ __align__(16) float A[NW * Q];     // originals (swizzled), reused for output
    // Per-warp region: [0:128) sorted column in BIT-REVERSED order,
    //                  [128:256) weight table in BIT-REVERSED order (+512 bytes).
    __shared__ __align__(16) float SW[NW * 256];

    int t    = threadIdx.x;
    int lane = t & 31;
    int w    = t >> 5;
    int sw   = w << 2;

    // bit-reversal helpers for 7-bit index idx = 4*lane + r:
    // rev7(idx) = rev2(r)*32 + rev5(lane)
    int rev5lane = (int)(__brev((unsigned)lane) >> 27);
    const int rev2r[4] = {0, 2, 1, 3};

    float* SWw = &SW[w * 256];

    // ---- per-warp bit-reversed weight table (independent of x; before sync) ----
    {
        float4 wf = *reinterpret_cast<const float4*>(&g_wt[lane << 2]);
        float wv4[4] = {wf.x, wf.y, wf.z, wf.w};
        #pragma unroll
        for (int r = 0; r < 4; r++)
            SWw[128 + rev2r[r] * 32 + rev5lane] = wv4[r];
    }

    // Column base: 8 consecutive flattened (b, h*w) columns per block.
    long long c0  = (long long)blockIdx.x * NW;
    int       b   = (int)(c0 >> 16);            // HW = 65536 columns per batch
    int       rem = (int)(c0 & (HW - 1));
    const float* xb = x   + (long long)b * (Q * (long long)HW) + rem;
    float*       ob = out + (long long)b * (Q * (long long)HW) + rem;

    // ---- Phase 1: coalesced load, transpose into swizzled SMEM ----
    {
        int q = t >> 1;            // 128 rows, 2 threads per row
        int g = t & 1;             // which float4 group: w_local = 4g .. 4g+3
        float4 f = *reinterpret_cast<const float4*>(xb + (long long)q * HW + 4 * g);
        float vv[4] = {f.x, f.y, f.z, f.w};
        #pragma unroll
        for (int j = 0; j < 4; j++) {
            int ww = 4 * g + j;
            A[ww * Q + (q ^ (ww << 2))] = vv[j];
        }
    }
    __syncthreads();

    // ---- Phase 2: read column (q = 4*lane + r), sort descending ----
    float4 cv = *reinterpret_cast<const float4*>(&A[w * Q + ((lane << 2) ^ sw)]);
    float v[4]    = {cv.x, cv.y, cv.z, cv.w};
    float orig[4] = {cv.x, cv.y, cv.z, cv.w};

    #pragma unroll
    for (int k = 2; k <= 128; k <<= 1) {
        #pragma unroll
        for (int j = k >> 1; j > 0; j >>= 1) {
            if (j >= 4) {
                #pragma unroll
                for (int r = 0; r < 4; r++) {
                    float o  = __shfl_xor_sync(0xffffffffu, v[r], j >> 2);
                    int   id = (lane << 2) + r;
                    bool keep_max = (((id & k) == 0) == ((id & j) == 0));
                    float mx = fmaxf(v[r], o), mn = fminf(v[r], o);
                    v[r] = keep_max ? mx : mn;
                }
            } else if (j == 2) {
                #pragma unroll
                for (int r = 0; r < 2; r++) {
                    int  id = (lane << 2) + r;
                    bool keep_max = ((id & k) == 0);
                    float a = v[r], bb = v[r + 2];
                    float mx = fmaxf(a, bb), mn = fminf(a, bb);
                    v[r]     = keep_max ? mx : mn;
                    v[r + 2] = keep_max ? mn : mx;
                }
            } else {  // j == 1
                #pragma unroll
                for (int r = 0; r < 4; r += 2) {
                    int  id = (lane << 2) + r;
                    bool keep_max = ((id & k) == 0);
                    float a = v[r], bb = v[r + 1];
                    float mx = fmaxf(a, bb), mn = fminf(a, bb);
                    v[r]     = keep_max ? mx : mn;
                    v[r + 1] = keep_max ? mn : mx;
                }
            }
        }
    }

    // ---- tie detection (once per warp): duplicates are adjacent after sort ----
    float vup = __shfl_up_sync(0xffffffffu, v[3], 1);
    bool adj = (v[0] == v[1]) | (v[1] == v[2]) | (v[2] == v[3]) |
               ((lane > 0) & (vup == v[0]));
    unsigned tieb = __ballot_sync(0xffffffffu, adj);

    // store sorted column BIT-REVERSED: SWw[rev7(p)] = sorted[p]
    #pragma unroll
    for (int r = 0; r < 4; r++)
        SWw[rev2r[r] * 32 + rev5lane] = v[r];
    __syncwarp();

    const char* Sb = reinterpret_cast<const char*>(SWw);
    float res[4];

    if (tieb == 0) {
        // ---- fast path: conflict-free bit-reversed binary search ----
        // probe byte offsets rev7(step-1)*4 and update bits rev7(step)*4
        #pragma unroll
        for (int r = 0; r < 4; r++) {
            float xv = orig[r];
            int rp = 0;  // byte offset = 4 * rev7(count_greater_so_far)
            if (*reinterpret_cast<const float*>(Sb + rp + 504) > xv) rp += 4;
            if (*reinterpret_cast<const float*>(Sb + rp + 496) > xv) rp += 8;
            if (*reinterpret_cast<const float*>(Sb + rp + 480) > xv) rp += 16;
            if (*reinterpret_cast<const float*>(Sb + rp + 448) > xv) rp += 32;
            if (*reinterpret_cast<const float*>(Sb + rp + 384) > xv) rp += 64;
            if (*reinterpret_cast<const float*>(Sb + rp + 256) > xv) rp += 128;
            if (*reinterpret_cast<const float*>(Sb + rp +   0) > xv) rp += 256;
            float wv = *reinterpret_cast<const float*>(Sb + rp + 512); // bit-rev wt
            float rs;
            asm("rsqrt.approx.f32 %0, %1;" : "=f"(rs) : "f"(__fmaf_rn(xv, xv, EPS)));
            res[r] = wv * rs;
        }
    } else {
        // ---- rare exact path: column has duplicate values ----
        const float* Acol = &A[w * Q];
        #pragma unroll
        for (int r = 0; r < 4; r++) {
            float xv = orig[r];
            int   i  = (lane << 2) + r;       // original q index of this element
            int gt = 0, eq = 0;
            for (int jj = 0; jj < Q; jj++) {
                float a = Acol[jj ^ sw];
                gt += (a > xv) ? 1 : 0;
                eq += ((a == xv) && (jj < i)) ? 1 : 0;
            }
            int rank = gt + eq;
            float wv = SWw[128 + (int)(__brev((unsigned)rank) >> 25)];
            float rs;
            asm("rsqrt.approx.f32 %0, %1;" : "=f"(rs) : "f"(__fmaf_rn(xv, xv, EPS)));
            res[r] = wv * rs;
        }
    }

    // all lanes of this warp are done reading A -> safe to overwrite own column
    __syncwarp();
    *reinterpret_cast<float4*>(&A[w * Q + ((lane << 2) ^ sw)]) =
        make_float4(res[0], res[1], res[2], res[3]);
    __syncthreads();

    // ---- Phase 4: transpose back, coalesced store ----
    {
        int q = t >> 1;
        int g = t & 1;
        float o0 = A[(4 * g + 0) * Q + (q ^ ((4 * g + 0) << 2))];
        float o1 = A[(4 * g + 1) * Q + (q ^ ((4 * g + 1) << 2))];
        float o2 = A[(4 * g + 2) * Q + (q ^ ((4 * g + 2) << 2))];
        float o3 = A[(4 * g + 3) * Q + (q ^ ((4 * g + 3) << 2))];
        *reinterpret_cast<float4*>(ob + (long long)q * HW + 4 * g) =
            make_float4(o0, o1, o2, o3);
    }
}

// ---------------------------------------------------------------------------
extern "C" void kernel_launch(void* const* d_in, const int* in_sizes, int n_in,
                              void* d_out, int out_size) {
    const float* x  = (const float*)d_in[0];
    const float* wt = (const float*)d_in[1];
    if (n_in >= 2 && in_sizes[0] == Q) {  // defensive: metadata order swap
        const float* tmp = x; x = wt; wt = tmp;
    }
    float* out = (float*)d_out;

    softmax_wt_kernel<<<1, 32>>>(wt);

    // total columns = 8 * 256 * 256 = 524288; NW columns per block
    int total_cols = 8 * HW;
    int blocks = total_cols / NW;          // 65536
    rank_weight_kernel<<<blocks, THREADS>>>(x, out);
}

// round 11
// speedup vs baseline: 1.3119x; 1.1732x over previous
#include <cuda_runtime.h>

#define EPS 1e-6f
#define Q 128
#define HW 65536            // 256*256
#define NW 8                // columns (warps) per block
#define THREADS 256

__device__ float g_wt[Q];   // softmax(weights) * 128, precomputed once

// ---------------------------------------------------------------------------
// Prep kernel: one warp computes wt = softmax(weights) * 128
// ---------------------------------------------------------------------------
__global__ void softmax_wt_kernel(const float* __restrict__ w) {
    int l = threadIdx.x;                       // 0..31
    float v0 = w[l * 4 + 0], v1 = w[l * 4 + 1];
    float v2 = w[l * 4 + 2], v3 = w[l * 4 + 3];
    float m = fmaxf(fmaxf(v0, v1), fmaxf(v2, v3));
    #pragma unroll
    for (int o = 16; o; o >>= 1) m = fmaxf(m, __shfl_xor_sync(0xffffffffu, m, o));
    float e0 = expf(v0 - m), e1 = expf(v1 - m);
    float e2 = expf(v2 - m), e3 = expf(v3 - m);
    float s = e0 + e1 + e2 + e3;
    #pragma unroll
    for (int o = 16; o; o >>= 1) s += __shfl_xor_sync(0xffffffffu, s, o);
    float scale = 128.0f / s;
    g_wt[l * 4 + 0] = e0 * scale;
    g_wt[l * 4 + 1] = e1 * scale;
    g_wt[l * 4 + 2] = e2 * scale;
    g_wt[l * 4 + 3] = e3 * scale;
}

// ---------------------------------------------------------------------------
// Main kernel: block = 256 threads = 8 warps; each warp ranks one column of
// 128 values (dim q). Swizzled SMEM transpose, warp-register bitonic sort
// built from PREDICATED FMNMX compare-exchanges (1 alu op per element-level),
// bit-reversed conflict-free binary-search rank, ballot-gated exact tie path.
// ---------------------------------------------------------------------------
__global__ void __launch_bounds__(THREADS) rank_weight_kernel(
        const float* __restrict__ x, float* __restrict__ out) {
    __shared__ __align__(16) float A[NW * Q];   // originals (swizzled), reused for output
    __shared__ __align__(16) float S[NW * Q];   // sorted columns, BIT-REVERSED order
    __shared__ __align__(16) float wt_rev[Q];   // softmax weights, BIT-REVERSED order

    int t    = threadIdx.x;
    int lane = t & 31;
    int w    = t >> 5;
    int sw   = w << 2;

    // bit-reversal helpers for 7-bit index idx = 4*lane + r:
    // rev7(idx) = rev2(r)*32 + rev5(lane)
    int rev5lane = (int)(__brev((unsigned)lane) >> 27);
    const int rev2r[4] = {0, 2, 1, 3};

    // block-level bit-reversed weight table (filled before the transpose sync)
    if (t < Q) wt_rev[(int)(__brev((unsigned)t) >> 25)] = g_wt[t];

    // Column base: 8 consecutive flattened (b, h*w) columns per block.
    long long c0  = (long long)blockIdx.x * NW;
    int       b   = (int)(c0 >> 16);            // HW = 65536 columns per batch
    int       rem = (int)(c0 & (HW - 1));
    const float* xb = x   + (long long)b * (Q * (long long)HW) + rem;
    float*       ob = out + (long long)b * (Q * (long long)HW) + rem;

    // ---- Phase 1: coalesced load, transpose into swizzled SMEM ----
    {
        int q = t >> 1;            // 128 rows, 2 threads per row
        int g = t & 1;             // which float4 group: w_local = 4g .. 4g+3
        float4 f = *reinterpret_cast<const float4*>(xb + (long long)q * HW + 4 * g);
        float vv[4] = {f.x, f.y, f.z, f.w};
        #pragma unroll
        for (int j = 0; j < 4; j++) {
            int ww = 4 * g + j;
            A[ww * Q + (q ^ (ww << 2))] = vv[j];
        }
    }
    __syncthreads();

    // ---- Phase 2: read column (q = 4*lane + r), sort descending ----
    float4 cv = *reinterpret_cast<const float4*>(&A[w * Q + ((lane << 2) ^ sw)]);
    float v[4]    = {cv.x, cv.y, cv.z, cv.w};
    float orig[4] = {cv.x, cv.y, cv.z, cv.w};

    // Bitonic sort, descending. All compare-exchanges written as
    // `km ? fmaxf : fminf` so ptxas emits FMNMX with a predicate operand.
    // km depends only on lane bits (or is compile-time), hoisted per level.
    #pragma unroll
    for (int k = 2; k <= 128; k <<= 1) {
        #pragma unroll
        for (int j = k >> 1; j > 0; j >>= 1) {
            if (j >= 4) {
                // cross-lane butterfly (k >= 8 here): id&k, id&j are lane-only
                bool km = ((lane & (k >> 2)) == 0) == ((lane & (j >> 2)) == 0);
                #pragma unroll
                for (int r = 0; r < 4; r++) {
                    float o = __shfl_xor_sync(0xffffffffu, v[r], j >> 2);
                    v[r] = km ? fmaxf(v[r], o) : fminf(v[r], o);
                }
            } else if (j == 2) {
                // k >= 4 here: km lane-only
                bool km = ((lane & (k >> 2)) == 0);
                #pragma unroll
                for (int r = 0; r < 2; r++) {
                    float a = v[r], bb = v[r + 2];
                    v[r]     = km ? fmaxf(a, bb) : fminf(a, bb);
                    v[r + 2] = km ? fminf(a, bb) : fmaxf(a, bb);
                }
            } else {  // j == 1
                if (k == 2) {
                    // directions are compile-time: pair(0,1) desc, pair(2,3) asc
                    float a0 = v[0], b0 = v[1];
                    v[0] = fmaxf(a0, b0); v[1] = fminf(a0, b0);
                    float a2 = v[2], b2 = v[3];
                    v[2] = fminf(a2, b2); v[3] = fmaxf(a2, b2);
                } else {
                    bool km = ((lane & (k >> 2)) == 0);
                    #pragma unroll
                    for (int r = 0; r < 4; r += 2) {
                        float a = v[r], bb = v[r + 1];
                        v[r]     = km ? fmaxf(a, bb) : fminf(a, bb);
                        v[r + 1] = km ? fminf(a, bb) : fmaxf(a, bb);
                    }
                }
            }
        }
    }

    // ---- tie detection (once per warp): duplicates are adjacent after sort ----
    float vup = __shfl_up_sync(0xffffffffu, v[3], 1);
    bool adj = (v[0] == v[1]) | (v[1] == v[2]) | (v[2] == v[3]) |
               ((lane > 0) & (vup == v[0]));
    unsigned tieb = __ballot_sync(0xffffffffu, adj);

    // store sorted column BIT-REVERSED: Scol[rev7(p)] = sorted[p]
    float* Scol = &S[w * Q];
    #pragma unroll
    for (int r = 0; r < 4; r++)
        Scol[rev2r[r] * 32 + rev5lane] = v[r];
    __syncwarp();

    const char* Sb = reinterpret_cast<const char*>(Scol);
    const char* Wb = reinterpret_cast<const char*>(wt_rev);
    float res[4];

    if (tieb == 0) {
        // ---- fast path: conflict-free bit-reversed binary search ----
        // probe byte offsets rev7(step-1)*4, update bits rev7(step)*4
        float med = *reinterpret_cast<const float*>(Sb + 504);  // same for all r
        #pragma unroll
        for (int r = 0; r < 4; r++) {
            float xv = orig[r];
            int rp = (med > xv) ? 4 : 0;   // byte offset = 4 * rev7(count_greater)
            if (*reinterpret_cast<const float*>(Sb + rp + 496) > xv) rp += 8;
            if (*reinterpret_cast<const float*>(Sb + rp + 480) > xv) rp += 16;
            if (*reinterpret_cast<const float*>(Sb + rp + 448) > xv) rp += 32;
            if (*reinterpret_cast<const float*>(Sb + rp + 384) > xv) rp += 64;
            if (*reinterpret_cast<const float*>(Sb + rp + 256) > xv) rp += 128;
            if (*reinterpret_cast<const float*>(Sb + rp +   0) > xv) rp += 256;
            float wv = *reinterpret_cast<const float*>(Wb + rp);   // bit-rev wt
            float rs;
            asm("rsqrt.approx.f32 %0, %1;" : "=f"(rs) : "f"(__fmaf_rn(xv, xv, EPS)));
            res[r] = wv * rs;
        }
    } else {
        // ---- rare exact path: column has duplicate values ----
        const float* Acol = &A[w * Q];
        #pragma unroll
        for (int r = 0; r < 4; r++) {
            float xv = orig[r];
            int   i  = (lane << 2) + r;       // original q index of this element
            int gt = 0, eq = 0;
            for (int jj = 0; jj < Q; jj++) {
                float a = Acol[jj ^ sw];
                gt += (a > xv) ? 1 : 0;
                eq += ((a == xv) && (jj < i)) ? 1 : 0;
            }
            int rank = gt + eq;
            float wv = wt_rev[(int)(__brev((unsigned)rank) >> 25)];
            float rs;
            asm("rsqrt.approx.f32 %0, %1;" : "=f"(rs) : "f"(__fmaf_rn(xv, xv, EPS)));
            res[r] = wv * rs;
        }
    }

    // all lanes of this warp are done reading A -> safe to overwrite own column
    __syncwarp();
    *reinterpret_cast<float4*>(&A[w * Q + ((lane << 2) ^ sw)]) =
        make_float4(res[0], res[1], res[2], res[3]);
    __syncthreads();

    // ---- Phase 4: transpose back, coalesced store ----
    {
        int q = t >> 1;
        int g = t & 1;
        float o0 = A[(4 * g + 0) * Q + (q ^ ((4 * g + 0) << 2))];
        float o1 = A[(4 * g + 1) * Q + (q ^ ((4 * g + 1) << 2))];
        float o2 = A[(4 * g + 2) * Q + (q ^ ((4 * g + 2) << 2))];
        float o3 = A[(4 * g + 3) * Q + (q ^ ((4 * g + 3) << 2))];
        *reinterpret_cast<float4*>(ob + (long long)q * HW + 4 * g) =
            make_float4(o0, o1, o2, o3);
    }
}

// ---------------------------------------------------------------------------
extern "C" void kernel_launch(void* const* d_in, const int* in_sizes, int n_in,
                              void* d_out, int out_size) {
    const float* x  = (const float*)d_in[0];
    const float* wt = (const float*)d_in[1];
    if (n_in >= 2 && in_sizes[0] == Q) {  // defensive: metadata order swap
        const float* tmp = x; x = wt; wt = tmp;
    }
    float* out = (float*)d_out;

    softmax_wt_kernel<<<1, 32>>>(wt);

    // total columns = 8 * 256 * 256 = 524288; NW columns per block
    int total_cols = 8 * HW;
    int blocks = total_cols / NW;          // 65536
    rank_weight_kernel<<<blocks, THREADS>>>(x, out);
}

// round 12
// speedup vs baseline: 1.3127x; 1.0006x over previous
#include <cuda_runtime.h>

#define EPS 1e-6f
#define Q 128
#define HW 65536            // 256*256
#define NW 8                // columns (warps) per block
#define THREADS 256

__device__ float g_wt[Q];   // softmax(weights) * 128, precomputed once

// ---------------------------------------------------------------------------
// Prep kernel: one warp computes wt = softmax(weights) * 128
// ---------------------------------------------------------------------------
__global__ void softmax_wt_kernel(const float* __restrict__ w) {
    int l = threadIdx.x;                       // 0..31
    float v0 = w[l * 4 + 0], v1 = w[l * 4 + 1];
    float v2 = w[l * 4 + 2], v3 = w[l * 4 + 3];
    float m = fmaxf(fmaxf(v0, v1), fmaxf(v2, v3));
    #pragma unroll
    for (int o = 16; o; o >>= 1) m = fmaxf(m, __shfl_xor_sync(0xffffffffu, m, o));
    float e0 = expf(v0 - m), e1 = expf(v1 - m);
    float e2 = expf(v2 - m), e3 = expf(v3 - m);
    float s = e0 + e1 + e2 + e3;
    #pragma unroll
    for (int o = 16; o; o >>= 1) s += __shfl_xor_sync(0xffffffffu, s, o);
    float scale = 128.0f / s;
    g_wt[l * 4 + 0] = e0 * scale;
    g_wt[l * 4 + 1] = e1 * scale;
    g_wt[l * 4 + 2] = e2 * scale;
    g_wt[l * 4 + 3] = e3 * scale;
}

// ---------------------------------------------------------------------------
// Main kernel: block = 256 threads = 8 warps; each warp ranks one column of
// 128 values (dim q). Swizzled SMEM transpose, warp-register bitonic sort
// built from PREDICATED FMNMX compare-exchanges (1 alu op per element-level),
// bit-reversed conflict-free binary-search rank, ballot-gated exact tie path.
// ---------------------------------------------------------------------------
__global__ void __launch_bounds__(THREADS) rank_weight_kernel(
        const float* __restrict__ x, float* __restrict__ out) {
    __shared__ __align__(16) float A[NW * Q];   // originals (swizzled), reused for output
    __shared__ __align__(16) float S[NW * Q];   // sorted columns, BIT-REVERSED order
    __shared__ __align__(16) float wt_rev[Q];   // softmax weights, BIT-REVERSED order

    int t    = threadIdx.x;
    int lane = t & 31;
    int w    = t >> 5;
    int sw   = w << 2;

    // bit-reversal helpers for 7-bit index idx = 4*lane + r:
    // rev7(idx) = rev2(r)*32 + rev5(lane)
    int rev5lane = (int)(__brev((unsigned)lane) >> 27);
    const int rev2r[4] = {0, 2, 1, 3};

    // block-level bit-reversed weight table (filled before the transpose sync)
    if (t < Q) wt_rev[(int)(__brev((unsigned)t) >> 25)] = g_wt[t];

    // Column base: 8 consecutive flattened (b, h*w) columns per block.
    long long c0  = (long long)blockIdx.x * NW;
    int       b   = (int)(c0 >> 16);            // HW = 65536 columns per batch
    int       rem = (int)(c0 & (HW - 1));
    const float* xb = x   + (long long)b * (Q * (long long)HW) + rem;
    float*       ob = out + (long long)b * (Q * (long long)HW) + rem;

    // ---- Phase 1: coalesced load, transpose into swizzled SMEM ----
    {
        int q = t >> 1;            // 128 rows, 2 threads per row
        int g = t & 1;             // which float4 group: w_local = 4g .. 4g+3
        float4 f = *reinterpret_cast<const float4*>(xb + (long long)q * HW + 4 * g);
        float vv[4] = {f.x, f.y, f.z, f.w};
        #pragma unroll
        for (int j = 0; j < 4; j++) {
            int ww = 4 * g + j;
            A[ww * Q + (q ^ (ww << 2))] = vv[j];
        }
    }
    __syncthreads();

    // ---- Phase 2: read column (q = 4*lane + r), sort descending ----
    float4 cv = *reinterpret_cast<const float4*>(&A[w * Q + ((lane << 2) ^ sw)]);
    float v[4]    = {cv.x, cv.y, cv.z, cv.w};
    float orig[4] = {cv.x, cv.y, cv.z, cv.w};

    // Bitonic sort, descending. All compare-exchanges written as
    // `km ? fmaxf : fminf` so ptxas emits FMNMX with a predicate operand.
    // km depends only on lane bits (or is compile-time), hoisted per level.
    #pragma unroll
    for (int k = 2; k <= 128; k <<= 1) {
        #pragma unroll
        for (int j = k >> 1; j > 0; j >>= 1) {
            if (j >= 4) {
                // cross-lane butterfly (k >= 8 here): id&k, id&j are lane-only
                bool km = ((lane & (k >> 2)) == 0) == ((lane & (j >> 2)) == 0);
                #pragma unroll
                for (int r = 0; r < 4; r++) {
                    float o = __shfl_xor_sync(0xffffffffu, v[r], j >> 2);
                    v[r] = km ? fmaxf(v[r], o) : fminf(v[r], o);
                }
            } else if (j == 2) {
                // k >= 4 here: km lane-only
                bool km = ((lane & (k >> 2)) == 0);
                #pragma unroll
                for (int r = 0; r < 2; r++) {
                    float a = v[r], bb = v[r + 2];
                    v[r]     = km ? fmaxf(a, bb) : fminf(a, bb);
                    v[r + 2] = km ? fminf(a, bb) : fmaxf(a, bb);
                }
            } else {  // j == 1
                if (k == 2) {
                    // directions are compile-time: pair(0,1) desc, pair(2,3) asc
                    float a0 = v[0], b0 = v[1];
                    v[0] = fmaxf(a0, b0); v[1] = fminf(a0, b0);
                    float a2 = v[2], b2 = v[3];
                    v[2] = fminf(a2, b2); v[3] = fmaxf(a2, b2);
                } else {
                    bool km = ((lane & (k >> 2)) == 0);
                    #pragma unroll
                    for (int r = 0; r < 4; r += 2) {
                        float a = v[r], bb = v[r + 1];
                        v[r]     = km ? fmaxf(a, bb) : fminf(a, bb);
                        v[r + 1] = km ? fminf(a, bb) : fmaxf(a, bb);
                    }
                }
            }
        }
    }

    // ---- tie detection (once per warp): duplicates are adjacent after sort ----
    float vup = __shfl_up_sync(0xffffffffu, v[3], 1);
    bool adj = (v[0] == v[1]) | (v[1] == v[2]) | (v[2] == v[3]) |
               ((lane > 0) & (vup == v[0]));
    unsigned tieb = __ballot_sync(0xffffffffu, adj);

    // store sorted column BIT-REVERSED: Scol[rev7(p)] = sorted[p]
    float* Scol = &S[w * Q];
    #pragma unroll
    for (int r = 0; r < 4; r++)
        Scol[rev2r[r] * 32 + rev5lane] = v[r];
    __syncwarp();

    const char* Sb = reinterpret_cast<const char*>(Scol);
    const char* Wb = reinterpret_cast<const char*>(wt_rev);
    float res[4];

    if (tieb == 0) {
        // ---- fast path: conflict-free bit-reversed binary search ----
        // probe byte offsets rev7(step-1)*4, update bits rev7(step)*4
        float med = *reinterpret_cast<const float*>(Sb + 504);  // same for all r
        #pragma unroll
        for (int r = 0; r < 4; r++) {
            float xv = orig[r];
            int rp = (med > xv) ? 4 : 0;   // byte offset = 4 * rev7(count_greater)
            if (*reinterpret_cast<const float*>(Sb + rp + 496) > xv) rp += 8;
            if (*reinterpret_cast<const float*>(Sb + rp + 480) > xv) rp += 16;
            if (*reinterpret_cast<const float*>(Sb + rp + 448) > xv) rp += 32;
            if (*reinterpret_cast<const float*>(Sb + rp + 384) > xv) rp += 64;
            if (*reinterpret_cast<const float*>(Sb + rp + 256) > xv) rp += 128;
            if (*reinterpret_cast<const float*>(Sb + rp +   0) > xv) rp += 256;
            float wv = *reinterpret_cast<const float*>(Wb + rp);   // bit-rev wt
            float rs;
            asm("rsqrt.approx.f32 %0, %1;" : "=f"(rs) : "f"(__fmaf_rn(xv, xv, EPS)));
            res[r] = wv * rs;
        }
    } else {
        // ---- rare exact path: column has duplicate values ----
        const float* Acol = &A[w * Q];
        #pragma unroll
        for (int r = 0; r < 4; r++) {
            float xv = orig[r];
            int   i  = (lane << 2) + r;       // original q index of this element
            int gt = 0, eq = 0;
            for (int jj = 0; jj < Q; jj++) {
                float a = Acol[jj ^ sw];
                gt += (a > xv) ? 1 : 0;
                eq += ((a == xv) && (jj < i)) ? 1 : 0;
            }
            int rank = gt + eq;
            float wv = wt_rev[(int)(__brev((unsigned)rank) >> 25)];
            float rs;
            asm("rsqrt.approx.f32 %0, %1;" : "=f"(rs) : "f"(__fmaf_rn(xv, xv, EPS)));
            res[r] = wv * rs;
        }
    }

    // all lanes of this warp are done reading A -> safe to overwrite own column
    __syncwarp();
    *reinterpret_cast<float4*>(&A[w * Q + ((lane << 2) ^ sw)]) =
        make_float4(res[0], res[1], res[2], res[3]);
    __syncthreads();

    // ---- Phase 4: transpose back, coalesced store ----
    {
        int q = t >> 1;
        int g = t & 1;
        float o0 = A[(4 * g + 0) * Q + (q ^ ((4 * g + 0) << 2))];
        float o1 = A[(4 * g + 1) * Q + (q ^ ((4 * g + 1) << 2))];
        float o2 = A[(4 * g + 2) * Q + (q ^ ((4 * g + 2) << 2))];
        float o3 = A[(4 * g + 3) * Q + (q ^ ((4 * g + 3) << 2))];
        *reinterpret_cast<float4*>(ob + (long long)q * HW + 4 * g) =
            make_float4(o0, o1, o2, o3);
    }
}

// ---------------------------------------------------------------------------
extern "C" void kernel_launch(void* const* d_in, const int* in_sizes, int n_in,
                              void* d_out, int out_size) {
    const float* x  = (const float*)d_in[0];
    const float* wt = (const float*)d_in[1];
    if (n_in >= 2 && in_sizes[0] == Q) {  // defensive: metadata order swap
        const float* tmp = x; x = wt; wt = tmp;
    }
    float* out = (float*)d_out;

    softmax_wt_kernel<<<1, 32>>>(wt);

    // total columns = 8 * 256 * 256 = 524288; NW columns per block
    int total_cols = 8 * HW;
    int blocks = total_cols / NW;          // 65536
    rank_weight_kernel<<<blocks, THREADS>>>(x, out);
}

// round 13
// speedup vs baseline: 1.4548x; 1.1083x over previous
#include <cuda_runtime.h>

#define EPS 1e-6f
#define Q 128
#define HW 65536            // 256*256
#define NCOLS 16            // columns per block (2 per warp)
#define THREADS 256
#define ASTRIDE 132         // words per column in staging array A

__device__ float g_wt[Q];   // softmax(weights) * 128, precomputed once

__global__ void softmax_wt_kernel(const float* __restrict__ w) {
    int l = threadIdx.x;
    float v0 = w[l * 4 + 0], v1 = w[l * 4 + 1];
    float v2 = w[l * 4 + 2], v3 = w[l * 4 + 3];
    float m = fmaxf(fmaxf(v0, v1), fmaxf(v2, v3));
    #pragma unroll
    for (int o = 16; o; o >>= 1) m = fmaxf(m, __shfl_xor_sync(0xffffffffu, m, o));
    float e0 = expf(v0 - m), e1 = expf(v1 - m);
    float e2 = expf(v2 - m), e3 = expf(v3 - m);
    float s = e0 + e1 + e2 + e3;
    #pragma unroll
    for (int o = 16; o; o >>= 1) s += __shfl_xor_sync(0xffffffffu, s, o);
    float scale = 128.0f / s;
    g_wt[l * 4 + 0] = e0 * scale;
    g_wt[l * 4 + 1] = e1 * scale;
    g_wt[l * 4 + 2] = e2 * scale;
    g_wt[l * 4 + 3] = e3 * scale;
}

// compare-exchange helpers (predicated FMNMX form)
#define CE_D(i,jj) { float _a=v[i], _b=v[jj]; v[i]=fmaxf(_a,_b); v[jj]=fminf(_a,_b); }
#define CE_A(i,jj) { float _a=v[i], _b=v[jj]; v[i]=fminf(_a,_b); v[jj]=fmaxf(_a,_b); }
#define CE_P(i,jj,p) { float _a=v[i], _b=v[jj]; float _mx=fmaxf(_a,_b), _mn=fminf(_a,_b); \
                       v[i]=(p)?_mx:_mn; v[jj]=(p)?_mn:_mx; }
#define INREG_P(p) \
    CE_P(0,4,p) CE_P(1,5,p) CE_P(2,6,p) CE_P(3,7,p) \
    CE_P(0,2,p) CE_P(1,3,p) CE_P(4,6,p) CE_P(5,7,p) \
    CE_P(0,1,p) CE_P(2,3,p) CE_P(4,5,p) CE_P(6,7,p)
#define XSTAGE(jm, km) { \
    _Pragma("unroll") \
    for (int _r = 0; _r < 8; _r++) { \
        float _o = __shfl_xor_sync(0xffffffffu, v[_r], (jm)); \
        v[_r] = (km) ? fmaxf(v[_r], _o) : fminf(v[_r], _o); \
    } }

// ---------------------------------------------------------------------------
// 256 threads = 8 warps; each warp ranks TWO columns of 128 (lanes 0-15 ->
// col 2w, lanes 16-31 -> col 2w+1), 8 elements per lane (q = 8m+r).
// ---------------------------------------------------------------------------
__global__ void __launch_bounds__(THREADS) rank_weight_kernel(
        const float* __restrict__ x, float* __restrict__ out) {
    __shared__ __align__(16) float A[NCOLS * ASTRIDE];  // staging (orig, then results)
    __shared__ __align__(16) float S[8 * 256];          // sorted, bit-rev, A/B interleaved
    __shared__ __align__(16) float wt2[256];            // weights, bit-rev, dup even/odd

    int t    = threadIdx.x;
    int lane = t & 31;
    int w    = t >> 5;
    int h    = (lane >> 4) & 1;   // column half within warp
    int m    = lane & 15;         // lane index within column

    // bit-reversed, even/odd-duplicated weight table: wt2[2p+h'] = g_wt[rev7(p)]
    wt2[t] = g_wt[__brev((unsigned)(t >> 1)) >> 25];

    long long c0  = (long long)blockIdx.x * NCOLS;
    int       b   = (int)(c0 >> 16);
    int       rem = (int)(c0 & (HW - 1));
    const float* xb = x   + (long long)b * (Q * (long long)HW) + rem;
    float*       ob = out + (long long)b * (Q * (long long)HW) + rem;

    // ---- Phase 1: coalesced load, transpose into vec-swizzled SMEM ----
    // A[col][q] at word col*132 + 4*(vec ^ ((vec>>3)&1)) + (q&3), vec = q>>2
    {
        int q = t >> 1, g = t & 1;
        float4 f0 = *reinterpret_cast<const float4*>(xb + (long long)q * HW + 4 * g);
        float4 f1 = *reinterpret_cast<const float4*>(xb + (long long)q * HW + 8 + 4 * g);
        int vec   = q >> 2;
        int basew = 4 * (vec ^ ((vec >> 3) & 1)) + (q & 3) + 528 * g;
        float vv0[4] = {f0.x, f0.y, f0.z, f0.w};
        float vv1[4] = {f1.x, f1.y, f1.z, f1.w};
        #pragma unroll
        for (int j = 0; j < 4; j++) A[basew + 132 * j] = vv0[j];
        #pragma unroll
        for (int j = 0; j < 4; j++) A[basew + 1056 + 132 * j] = vv1[j];
    }
    __syncthreads();

    // ---- Phase 2: read own column slice (q = 8m..8m+7) ----
    int col  = 2 * w + h;
    int m2b  = (m >> 2) & 1;
    int w1   = col * ASTRIDE + 8 * m + 4 * m2b;        // vec 2m
    int w2   = col * ASTRIDE + 8 * m + 4 * (1 - m2b);  // vec 2m+1
    float4 ca = *reinterpret_cast<const float4*>(&A[w1]);
    float4 cb = *reinterpret_cast<const float4*>(&A[w2]);
    float v[8]    = {ca.x, ca.y, ca.z, ca.w, cb.x, cb.y, cb.z, cb.w};
    float orig[8] = {ca.x, ca.y, ca.z, ca.w, cb.x, cb.y, cb.z, cb.w};

    // ---- bitonic sort over i = 8m + r, descending ----
    CE_D(0,1) CE_A(2,3) CE_D(4,5) CE_A(6,7)                     // k=2
    CE_D(0,2) CE_D(1,3) CE_A(4,6) CE_A(5,7)                     // k=4
    CE_D(0,1) CE_D(2,3) CE_A(4,5) CE_A(6,7)
    {   // k=8
        bool d8 = (m & 1) == 0;
        INREG_P(d8)
    }
    {   // k=16
        bool k16 = (m & 2) == 0;
        XSTAGE(1, k16 == ((m & 1) == 0))
        INREG_P(k16)
    }
    {   // k=32
        bool k32 = (m & 4) == 0;
        XSTAGE(2, k32 == ((m & 2) == 0))
        XSTAGE(1, k32 == ((m & 1) == 0))
        INREG_P(k32)
    }
    {   // k=64
        bool k64 = (m & 8) == 0;
        XSTAGE(4, k64 == ((m & 4) == 0))
        XSTAGE(2, k64 == ((m & 2) == 0))
        XSTAGE(1, k64 == ((m & 1) == 0))
        INREG_P(k64)
    }
    // k=128: (i&128)==0 always -> direction from j bit only
    XSTAGE(8, (m & 8) == 0)
    XSTAGE(4, (m & 4) == 0)
    XSTAGE(2, (m & 2) == 0)
    XSTAGE(1, (m & 1) == 0)
    CE_D(0,4) CE_D(1,5) CE_D(2,6) CE_D(3,7)
    CE_D(0,2) CE_D(1,3) CE_D(4,6) CE_D(5,7)
    CE_D(0,1) CE_D(2,3) CE_D(4,5) CE_D(6,7)

    // ---- tie detection per column half ----
    float vup = __shfl_up_sync(0xffffffffu, v[7], 1);
    bool adj = (v[0]==v[1]) | (v[1]==v[2]) | (v[2]==v[3]) | (v[3]==v[4]) |
               (v[4]==v[5]) | (v[5]==v[6]) | (v[6]==v[7]) |
               ((m > 0) & (vup == v[0]));
    unsigned tieb  = __ballot_sync(0xffffffffu, adj);
    unsigned mytie = (tieb >> (h << 4)) & 0xFFFFu;

    // ---- store sorted, bit-reversed, A/B interleaved ----
    // word = 2*rev7(8m+r) + h = 32*rev3(r) + 2*rev4(m) + h
    float* Sw = &S[w * 256];
    int sbase = 2 * (int)(__brev((unsigned)m) >> 28) + h;
    Sw[sbase +   0] = v[0];
    Sw[sbase + 128] = v[1];
    Sw[sbase +  64] = v[2];
    Sw[sbase + 192] = v[3];
    Sw[sbase +  32] = v[4];
    Sw[sbase + 160] = v[5];
    Sw[sbase +  96] = v[6];
    Sw[sbase + 224] = v[7];
    __syncwarp();

    const char* Sb = reinterpret_cast<const char*>(Sw) + (h << 2);
    const char* Wb = reinterpret_cast<const char*>(wt2) + (h << 2);

    if (mytie == 0) {
        // ---- fast path: bit-reversed conflict-free binary search ----
        // byte offset of sorted[p] (rel. Sb) = 8*rev7(p); rank stored as rp
        float med = *reinterpret_cast<const float*>(Sb + 1008);   // step-64 probe
        float p2a = *reinterpret_cast<const float*>(Sb +  992);   // step-32 pair
        float p2b = *reinterpret_cast<const float*>(Sb + 1000);
        #pragma unroll
        for (int r = 0; r < 8; r++) {
            float xv = orig[r];
            int rp = (med > xv) ? 8 : 0;
            float p2 = rp ? p2b : p2a;
            if (p2 > xv) rp += 16;
            if (*reinterpret_cast<const float*>(Sb + rp + 960) > xv) rp += 32;
            if (*reinterpret_cast<const float*>(Sb + rp + 896) > xv) rp += 64;
            if (*reinterpret_cast<const float*>(Sb + rp + 768) > xv) rp += 128;
            if (*reinterpret_cast<const float*>(Sb + rp + 512) > xv) rp += 256;
            if (*reinterpret_cast<const float*>(Sb + rp      ) > xv) rp += 512;
            float wv = *reinterpret_cast<const float*>(Wb + rp);  // bit-rev weight
            float rs;
            asm("rsqrt.approx.f32 %0, %1;" : "=f"(rs) : "f"(__fmaf_rn(xv, xv, EPS)));
            orig[r] = wv * rs;                                    // reuse as result
        }
    } else {
        // ---- rare exact path: column has duplicate values ----
        int colw = col * ASTRIDE;
        #pragma unroll 1
        for (int r = 0; r < 8; r++) {
            float xv = orig[r];
            int   i  = 8 * m + r;
            int gt = 0, eq = 0;
            for (int jj = 0; jj < Q; jj++) {
                int vec = jj >> 2;
                float a = A[colw + 4 * (vec ^ ((vec >> 3) & 1)) + (jj & 3)];
                gt += (a > xv) ? 1 : 0;
                eq += ((a == xv) && (jj < i)) ? 1 : 0;
            }
            int rank = gt + eq;
            float wv = wt2[2 * (int)(__brev((unsigned)rank) >> 25) + h];
            float rs;
            asm("rsqrt.approx.f32 %0, %1;" : "=f"(rs) : "f"(__fmaf_rn(xv, xv, EPS)));
            orig[r] = wv * rs;
        }
    }

    // all lanes of this warp done reading their columns of A -> overwrite
    __syncwarp();
    *reinterpret_cast<float4*>(&A[w1]) = make_float4(orig[0], orig[1], orig[2], orig[3]);
    *reinterpret_cast<float4*>(&A[w2]) = make_float4(orig[4], orig[5], orig[6], orig[7]);
    __syncthreads();

    // ---- Phase 4: transpose back, coalesced store ----
    {
        int q = t >> 1, g = t & 1;
        int vec   = q >> 2;
        int basew = 4 * (vec ^ ((vec >> 3) & 1)) + (q & 3) + 528 * g;
        float o0 = A[basew +   0], o1 = A[basew + 132];
        float o2 = A[basew + 264], o3 = A[basew + 396];
        *reinterpret_cast<float4*>(ob + (long long)q * HW + 4 * g) =
            make_float4(o0, o1, o2, o3);
        float p0 = A[basew + 1056], p1 = A[basew + 1188];
        float p2 = A[basew + 1320], p3 = A[basew + 1452];
        *reinterpret_cast<float4*>(ob + (long long)q * HW + 8 + 4 * g) =
            make_float4(p0, p1, p2, p3);
    }
}

// ---------------------------------------------------------------------------
extern "C" void kernel_launch(void* const* d_in, const int* in_sizes, int n_in,
                              void* d_out, int out_size) {
    const float* x  = (const float*)d_in[0];
    const float* wt = (const float*)d_in[1];
    if (n_in >= 2 && in_sizes[0] == Q) {  // defensive: metadata order swap
        const float* tmp = x; x = wt; wt = tmp;
    }
    float* out = (float*)d_out;

    softmax_wt_kernel<<<1, 32>>>(wt);

    int total_cols = 8 * HW;               // 524288
    int blocks = total_cols / NCOLS;       // 32768
    rank_weight_kernel<<<blocks, THREADS>>>(x, out);
}

// round 14
// speedup vs baseline: 1.6379x; 1.1258x over previous
#include <cuda_runtime.h>

#define EPS 1e-6f
#define Q 128
#define HW 65536            // 256*256
#define NCOLS 16            // columns per block (2 per warp)
#define THREADS 256
#define ASTRIDE 132         // words per column in staging array A

__device__ float g_wt[Q];   // softmax(weights) * 128, precomputed once

__global__ void softmax_wt_kernel(const float* __restrict__ w) {
    int l = threadIdx.x;
    float v0 = w[l * 4 + 0], v1 = w[l * 4 + 1];
    float v2 = w[l * 4 + 2], v3 = w[l * 4 + 3];
    float m = fmaxf(fmaxf(v0, v1), fmaxf(v2, v3));
    #pragma unroll
    for (int o = 16; o; o >>= 1) m = fmaxf(m, __shfl_xor_sync(0xffffffffu, m, o));
    float e0 = expf(v0 - m), e1 = expf(v1 - m);
    float e2 = expf(v2 - m), e3 = expf(v3 - m);
    float s = e0 + e1 + e2 + e3;
    #pragma unroll
    for (int o = 16; o; o >>= 1) s += __shfl_xor_sync(0xffffffffu, s, o);
    float scale = 128.0f / s;
    g_wt[l * 4 + 0] = e0 * scale;
    g_wt[l * 4 + 1] = e1 * scale;
    g_wt[l * 4 + 2] = e2 * scale;
    g_wt[l * 4 + 3] = e3 * scale;
}

// orderable-uint transform: monotonic with float order (no NaN in inputs)
__device__ __forceinline__ unsigned ford(unsigned b) {
    return b ^ ((unsigned)(((int)b) >> 31) | 0x80000000u);
}

// unsigned compare-exchange helpers (predicated IMNMX form)
#define UCE_D(i,jj) { unsigned _a=v[i], _b=v[jj]; v[i]=max(_a,_b); v[jj]=min(_a,_b); }
#define UCE_A(i,jj) { unsigned _a=v[i], _b=v[jj]; v[i]=min(_a,_b); v[jj]=max(_a,_b); }
#define UCE_P(i,jj,p) { unsigned _a=v[i], _b=v[jj]; unsigned _mx=max(_a,_b), _mn=min(_a,_b); \
                        v[i]=(p)?_mx:_mn; v[jj]=(p)?_mn:_mx; }
#define UINREG_P(p) \
    UCE_P(0,4,p) UCE_P(1,5,p) UCE_P(2,6,p) UCE_P(3,7,p) \
    UCE_P(0,2,p) UCE_P(1,3,p) UCE_P(4,6,p) UCE_P(5,7,p) \
    UCE_P(0,1,p) UCE_P(2,3,p) UCE_P(4,5,p) UCE_P(6,7,p)
#define UXSTAGE(jm, km) { \
    _Pragma("unroll") \
    for (int _r = 0; _r < 8; _r++) { \
        unsigned _o = __shfl_xor_sync(0xffffffffu, v[_r], (jm)); \
        v[_r] = (km) ? max(v[_r], _o) : min(v[_r], _o); \
    } }

// ---------------------------------------------------------------------------
// 256 threads = 8 warps; each warp ranks TWO columns of 128 (lanes 0-15 ->
// col 2w, lanes 16-31 -> col 2w+1), 8 elements per lane (q = 8m+r).
// Keys = ford(x) with low 7 bits = 127-idx  ->  sort IS the rank+provenance.
// ---------------------------------------------------------------------------
__global__ void __launch_bounds__(THREADS) rank_weight_kernel(
        const float* __restrict__ x, float* __restrict__ out) {
    __shared__ __align__(16) float A[NCOLS * ASTRIDE];  // originals, then results (unswizzled)

    int t    = threadIdx.x;
    int lane = t & 31;
    int w    = t >> 5;
    int h    = (lane >> 4) & 1;   // column half within warp
    int m    = lane & 15;         // lane index within column

    // per-lane weight registers for ranks 8m..8m+7 (L1-cached global loads)
    float4 wta = *reinterpret_cast<const float4*>(&g_wt[8 * m]);
    float4 wtb = *reinterpret_cast<const float4*>(&g_wt[8 * m + 4]);
    float wv[8] = {wta.x, wta.y, wta.z, wta.w, wtb.x, wtb.y, wtb.z, wtb.w};

    long long c0  = (long long)blockIdx.x * NCOLS;
    int       b   = (int)(c0 >> 16);
    int       rem = (int)(c0 & (HW - 1));
    const float* xb = x   + (long long)b * (Q * (long long)HW) + rem;
    float*       ob = out + (long long)b * (Q * (long long)HW) + rem;

    // ---- Phase 1: coalesced load, transpose into unswizzled SMEM ----
    // A[col][q] at word col*132 + q  (conflict-free for these access patterns)
    {
        int q = t >> 1, g = t & 1;
        float4 f0 = *reinterpret_cast<const float4*>(xb + (long long)q * HW + 4 * g);
        float4 f1 = *reinterpret_cast<const float4*>(xb + (long long)q * HW + 8 + 4 * g);
        float vv0[4] = {f0.x, f0.y, f0.z, f0.w};
        float vv1[4] = {f1.x, f1.y, f1.z, f1.w};
        #pragma unroll
        for (int j = 0; j < 4; j++) A[(4 * g + j) * ASTRIDE + q] = vv0[j];
        #pragma unroll
        for (int j = 0; j < 4; j++) A[(8 + 4 * g + j) * ASTRIDE + q] = vv1[j];
    }
    __syncthreads();

    // ---- Phase 2: read own column slice (q = 8m..8m+7), build keys ----
    int colw = (2 * w + h) * ASTRIDE;
    float4 ca = *reinterpret_cast<const float4*>(&A[colw + 8 * m]);
    float4 cb = *reinterpret_cast<const float4*>(&A[colw + 8 * m + 4]);
    unsigned v[8];
    {
        int base = 127 - 8 * m;
        float xs[8] = {ca.x, ca.y, ca.z, ca.w, cb.x, cb.y, cb.z, cb.w};
        #pragma unroll
        for (int r = 0; r < 8; r++)
            v[r] = (ford(__float_as_uint(xs[r])) & 0xFFFFFF80u) + (unsigned)(base - r);
    }

    // ---- bitonic sort over i = 8m + r, descending on keys ----
    UCE_D(0,1) UCE_A(2,3) UCE_D(4,5) UCE_A(6,7)                 // k=2
    UCE_D(0,2) UCE_D(1,3) UCE_A(4,6) UCE_A(5,7)                 // k=4
    UCE_D(0,1) UCE_D(2,3) UCE_A(4,5) UCE_A(6,7)
    {   bool d8 = (m & 1) == 0;                                  // k=8
        UINREG_P(d8)
    }
    {   bool k16 = (m & 2) == 0;                                 // k=16
        UXSTAGE(1, k16 == ((m & 1) == 0))
        UINREG_P(k16)
    }
    {   bool k32 = (m & 4) == 0;                                 // k=32
        UXSTAGE(2, k32 == ((m & 2) == 0))
        UXSTAGE(1, k32 == ((m & 1) == 0))
        UINREG_P(k32)
    }
    {   bool k64 = (m & 8) == 0;                                 // k=64
        UXSTAGE(4, k64 == ((m & 4) == 0))
        UXSTAGE(2, k64 == ((m & 2) == 0))
        UXSTAGE(1, k64 == ((m & 1) == 0))
        UINREG_P(k64)
    }
    UXSTAGE(8, (m & 8) == 0)                                     // k=128
    UXSTAGE(4, (m & 4) == 0)
    UXSTAGE(2, (m & 2) == 0)
    UXSTAGE(1, (m & 1) == 0)
    UCE_D(0,4) UCE_D(1,5) UCE_D(2,6) UCE_D(3,7)
    UCE_D(0,2) UCE_D(1,3) UCE_D(4,6) UCE_D(5,7)
    UCE_D(0,1) UCE_D(2,3) UCE_D(4,5) UCE_D(6,7)

    // ---- clobber detection: adjacent sorted keys with equal high-25 bits ----
    unsigned knext = __shfl_down_sync(0xffffffffu, v[0], 1);   // next lane's first
    unsigned kprev = __shfl_up_sync(0xffffffffu, v[7], 1);     // prev lane's last
    bool fl0 = (v[0] ^ v[1]) < 128u;
    bool fl1 = (v[1] ^ v[2]) < 128u;
    bool fl2 = (v[2] ^ v[3]) < 128u;
    bool fl3 = (v[3] ^ v[4]) < 128u;
    bool fl4 = (v[4] ^ v[5]) < 128u;
    bool fl5 = (v[5] ^ v[6]) < 128u;
    bool fl6 = (v[6] ^ v[7]) < 128u;
    bool flagB = (m < 15) && ((v[7] ^ knext) < 128u);
    unsigned fpv = __shfl_up_sync(0xffffffffu, (unsigned)flagB, 1);
    bool fprev = (m > 0) && (fpv != 0u);

    bool fwp[8] = {fprev, fl0, fl1, fl2, fl3, fl4, fl5, fl6};
    bool fwn[8] = {fl0, fl1, fl2, fl3, fl4, fl5, fl6, flagB};
    bool anyf = false, badf = false;
    #pragma unroll
    for (int r = 0; r < 8; r++) { anyf |= (fwp[r] | fwn[r]); badf |= (fwp[r] & fwn[r]); }

    unsigned fb = __ballot_sync(0xffffffffu, anyf);
    if (fb) {
        unsigned bb = __ballot_sync(0xffffffffu, badf);
        if (bb) {
            // run >= 3 somewhere (ultra rare): exact recompute of all ranks
            #pragma unroll 1
            for (int r = 0; r < 8; r++) {
                int idx = (int)((~v[r]) & 127u);
                unsigned us = ford(__float_as_uint(A[colw + idx]));
                int gt = 0, eq = 0;
                for (int jj = 0; jj < Q; jj++) {
                    unsigned ua = ford(__float_as_uint(A[colw + jj]));
                    gt += (ua > us) ? 1 : 0;
                    eq += ((ua == us) && (jj < idx)) ? 1 : 0;
                }
                wv[r] = g_wt[gt + eq];
            }
        } else {
            // pair runs only: exact 2-element fix (rare, predicated)
            #pragma unroll
            for (int r = 0; r < 8; r++) {
                if (fwp[r] | fwn[r]) {
                    bool lo = fwp[r];
                    unsigned pk = lo ? (r > 0 ? v[r - 1] : kprev)
                                     : (r < 7 ? v[r + 1] : knext);
                    int idx  = (int)((~v[r]) & 127u);
                    int pidx = (int)((~pk)   & 127u);
                    unsigned us = ford(__float_as_uint(A[colw + idx]));
                    unsigned up = ford(__float_as_uint(A[colw + pidx]));
                    bool mefirst = (us > up) || ((us == up) && (idx < pidx));
                    int p    = 8 * m + r;
                    int pmin = lo ? p - 1 : p;
                    wv[r] = g_wt[mefirst ? pmin : pmin + 1];
                }
            }
        }
        __syncwarp();   // fix reads of A must precede scatter writes
    }

    // ---- scatter read-modify-write: A[idx] = wt[rank] * rsqrt(x^2 + eps) ----
    // each (lane, slot) owns exactly one address -> no cross-lane hazard
    #pragma unroll
    for (int r = 0; r < 8; r++) {
        int addr = colw + (int)((~v[r]) & 127u);
        float xv = A[addr];
        float rs;
        asm("rsqrt.approx.f32 %0, %1;" : "=f"(rs) : "f"(__fmaf_rn(xv, xv, EPS)));
        A[addr] = wv[r] * rs;
    }
    __syncthreads();

    // ---- Phase 4: transpose back, coalesced store ----
    {
        int q = t >> 1, g = t & 1;
        float o0 = A[(4 * g + 0) * ASTRIDE + q], o1 = A[(4 * g + 1) * ASTRIDE + q];
        float o2 = A[(4 * g + 2) * ASTRIDE + q], o3 = A[(4 * g + 3) * ASTRIDE + q];
        *reinterpret_cast<float4*>(ob + (long long)q * HW + 4 * g) =
            make_float4(o0, o1, o2, o3);
        float p0 = A[(8 + 4 * g + 0) * ASTRIDE + q], p1 = A[(8 + 4 * g + 1) * ASTRIDE + q];
        float p2 = A[(8 + 4 * g + 2) * ASTRIDE + q], p3 = A[(8 + 4 * g + 3) * ASTRIDE + q];
        *reinterpret_cast<float4*>(ob + (long long)q * HW + 8 + 4 * g) =
            make_float4(p0, p1, p2, p3);
    }
}

// ---------------------------------------------------------------------------
extern "C" void kernel_launch(void* const* d_in, const int* in_sizes, int n_in,
                              void* d_out, int out_size) {
    const float* x  = (const float*)d_in[0];
    const float* wt = (const float*)d_in[1];
    if (n_in >= 2 && in_sizes[0] == Q) {  // defensive: metadata order swap
        const float* tmp = x; x = wt; wt = tmp;
    }
    float* out = (float*)d_out;

    softmax_wt_kernel<<<1, 32>>>(wt);

    int total_cols = 8 * HW;               // 524288
    int blocks = total_cols / NCOLS;       // 32768
    rank_weight_kernel<<<blocks, THREADS>>>(x, out);
}